// round 12
// baseline (speedup 1.0000x reference)
#include <cuda_runtime.h>
#include <cuda_bf16.h>
#include <cstdint>

#define N_NODES 50000
#define F_IN    128
#define F_HID   512
#define CAP     128            // fixed bucket capacity per node
#define MAX_OVF 4096           // overflow list capacity (never used in practice)

// ---------------------------------------------------------------------------
// Scratch (__device__ globals; allocation-free rule)
// ---------------------------------------------------------------------------
__device__ __align__(16) __nv_bfloat16 g_xs[N_NODES * 256];           // x split, interleaved:
                                                                      // [node][c=0..31][hi(4),lo(4)]
__device__ __align__(16) __nv_bfloat16 g_h0_hi[N_NODES * F_IN];       // split h0
__device__ __align__(16) __nv_bfloat16 g_h0_lo[N_NODES * F_IN];
__device__ __align__(16) __nv_bfloat16 g_w1t_hi[F_HID * F_IN];        // W1^T split [512,128]
__device__ __align__(16) __nv_bfloat16 g_w1t_lo[F_HID * F_IN];
__device__ __align__(16) __nv_bfloat16 g_w2t_hi[F_IN * F_HID];        // W2^T split [128,512]
__device__ __align__(16) __nv_bfloat16 g_w2t_lo[F_IN * F_HID];
__device__ int g_cur[N_NODES];                 // per-node fill counters (=degree)
__device__ int g_bucket[N_NODES * CAP];        // fixed-capacity buckets of src ids
__device__ int g_ovf[2 * MAX_OVF];             // overflow (src,dst) pairs
__device__ int g_ovf_cnt;
__device__ int g_idx_is64;

__device__ __forceinline__ uint32_t smem_to_u32(const void* p) {
    uint32_t a;
    asm("{ .reg .u64 t; cvta.to.shared.u64 t, %1; cvt.u32.u64 %0, t; }"
        : "=r"(a) : "l"(p));
    return a;
}
__device__ __forceinline__ uint32_t pack_bf2(__nv_bfloat16 a, __nv_bfloat16 b) {
    __nv_bfloat162 t(a, b);
    return *reinterpret_cast<uint32_t*>(&t);
}
__device__ __forceinline__ float2 unpack_bf2(uint32_t w) {
    __nv_bfloat162 t = *reinterpret_cast<__nv_bfloat162*>(&w);
    return __bfloat1622float2(t);
}
__device__ __forceinline__ uint32_t sw128(uint32_t byte_off) {
    return byte_off ^ ((byte_off >> 3) & 0x70);
}
// 128x128 bf16 tile: two 128x64 column blocks (16KB each, 128B rows, SW128)
__device__ __forceinline__ uint32_t toff128(int r, int k) {
    return (uint32_t)((k >> 6) * 16384) + sw128((uint32_t)(r * 128 + (k & 63) * 2));
}
// 64x128 bf16 tile (W1 chunk): two 64x64 column blocks (8KB each)
__device__ __forceinline__ uint32_t t64r(int r, int k) {
    return (uint32_t)((k >> 6) * 8192) + sw128((uint32_t)(r * 128 + (k & 63) * 2));
}
// 128x64 bf16 tile (H, W2 chunk): single block, 128B rows
__device__ __forceinline__ uint32_t t64c(int r, int k) {
    return sw128((uint32_t)(r * 128 + k * 2));
}

__device__ __forceinline__ void ldmx4(uint32_t* r, uint32_t addr) {
    asm volatile("ldmatrix.sync.aligned.m8n8.x4.shared.b16 {%0,%1,%2,%3}, [%4];"
                 : "=r"(r[0]), "=r"(r[1]), "=r"(r[2]), "=r"(r[3]) : "r"(addr));
}
__device__ __forceinline__ void ldmx2(uint32_t* r, uint32_t addr) {
    asm volatile("ldmatrix.sync.aligned.m8n8.x2.shared.b16 {%0,%1}, [%2];"
                 : "=r"(r[0]), "=r"(r[1]) : "r"(addr));
}
__device__ __forceinline__ void mma16816(float* c, const uint32_t* a, const uint32_t* b) {
    asm volatile(
        "mma.sync.aligned.m16n8k16.row.col.f32.bf16.bf16.f32 "
        "{%0,%1,%2,%3}, {%4,%5,%6,%7}, {%8,%9}, {%0,%1,%2,%3};"
        : "+f"(c[0]), "+f"(c[1]), "+f"(c[2]), "+f"(c[3])
        : "r"(a[0]), "r"(a[1]), "r"(a[2]), "r"(a[3]), "r"(b[0]), "r"(b[1]));
}
#define CP_ASYNC16(dst_u32, src_ptr) \
    asm volatile("cp.async.cg.shared.global [%0], [%1], 16;" \
                 :: "r"(dst_u32), "l"(src_ptr) : "memory")
#define CP_COMMIT() asm volatile("cp.async.commit_group;" ::: "memory")
#define CP_WAIT1()  asm volatile("cp.async.wait_group 1;"  ::: "memory")

__device__ __forceinline__ int load_idx(const void* ei, int i) {
    return g_idx_is64 ? (int)((const long long*)ei)[i] : ((const int*)ei)[i];
}

// ---------------------------------------------------------------------------
// Kernel A: zero bucket counters + overflow counter + dtype detection
// ---------------------------------------------------------------------------
__global__ void zero_kernel(const int* __restrict__ ei_words)
{
    int i = blockIdx.x * blockDim.x + threadIdx.x;
    if (i < N_NODES) g_cur[i] = 0;
    if (i == 0) {
        g_ovf_cnt = 0;
        int is64 = 1;
        #pragma unroll
        for (int k = 0; k < 64; k++) {
            if (ei_words[2 * k + 1] != 0) { is64 = 0; break; }
        }
        g_idx_is64 = is64;
    }
}

// ---------------------------------------------------------------------------
// Kernel A2: split x into interleaved hi/lo chunks of 4 features.
//   g_xs[node*256 + c*8 + 0..3] = hi(x[node, 4c..4c+3])
//   g_xs[node*256 + c*8 + 4..7] = lo(...)
// ---------------------------------------------------------------------------
__global__ void splitx_kernel(const float* __restrict__ x)
{
    int idx = blockIdx.x * blockDim.x + threadIdx.x;   // chunk id
    if (idx >= N_NODES * 32) return;
    float4 v = reinterpret_cast<const float4*>(x)[idx];
    __nv_bfloat16 h0 = __float2bfloat16(v.x);
    __nv_bfloat16 h1 = __float2bfloat16(v.y);
    __nv_bfloat16 h2 = __float2bfloat16(v.z);
    __nv_bfloat16 h3 = __float2bfloat16(v.w);
    uint4 o;
    o.x = pack_bf2(h0, h1);
    o.y = pack_bf2(h2, h3);
    o.z = pack_bf2(__float2bfloat16(v.x - __bfloat162float(h0)),
                   __float2bfloat16(v.y - __bfloat162float(h1)));
    o.w = pack_bf2(__float2bfloat16(v.z - __bfloat162float(h2)),
                   __float2bfloat16(v.w - __bfloat162float(h3)));
    reinterpret_cast<uint4*>(g_xs)[idx] = o;
}

// ---------------------------------------------------------------------------
// Kernel B: single-pass bucketing (atomicAdd doubles as histogram), 8/thread.
// ---------------------------------------------------------------------------
__global__ void bucket_kernel(const void* __restrict__ ei, int n_edges)
{
    int base = blockIdx.x * 2048;
    #pragma unroll
    for (int k = 0; k < 8; k++) {
        int e = base + k * 256 + threadIdx.x;
        if (e < n_edges) {
            int s = load_idx(ei, e);
            int d = load_idx(ei, n_edges + e);
            if (s >= 0 && s < N_NODES && d >= 0 && d < N_NODES) {
                int pos = atomicAdd(&g_cur[d], 1);
                if (pos < CAP) {
                    g_bucket[d * CAP + pos] = s;
                } else {
                    int o = atomicAdd(&g_ovf_cnt, 1);
                    if (o < MAX_OVF) {
                        g_ovf[2 * o] = s;
                        g_ovf[2 * o + 1] = d;
                    }
                }
            }
        }
    }
}

// ---------------------------------------------------------------------------
// Kernel: weight transpose + hi/lo bf16 split. out[n*K+k] = split(W[k*N+n]).
// ---------------------------------------------------------------------------
__global__ void transpose_split_kernel(const float* __restrict__ W, int K, int N,
                                       __nv_bfloat16* __restrict__ out_hi,
                                       __nv_bfloat16* __restrict__ out_lo)
{
    int idx = blockIdx.x * blockDim.x + threadIdx.x;
    if (idx >= K * N) return;
    int n = idx / K, k = idx % K;
    float v = W[(size_t)k * N + n];
    __nv_bfloat16 h = __float2bfloat16(v);
    out_hi[idx] = h;
    out_lo[idx] = __float2bfloat16(v - __bfloat162float(h));
}

// ---------------------------------------------------------------------------
// Kernel E: gather-accumulate, warp per node. Neighbor features come from the
// pre-split g_xs (one LDG.128 per edge-lane, hi+lo in one load). Self term
// stays exact fp32 from x.
// ---------------------------------------------------------------------------
__global__ __launch_bounds__(256)
void gather_kernel(const float* __restrict__ x,
                   const float* __restrict__ eps,
                   __nv_bfloat16* __restrict__ h_hi,
                   __nv_bfloat16* __restrict__ h_lo)
{
    const int warp = (blockIdx.x * blockDim.x + threadIdx.x) >> 5;
    if (warp >= N_NODES) return;
    const int lane = threadIdx.x & 31;

    const int deg  = min(g_cur[warp], CAP);
    const int base = warp * CAP;
    const float s = 1.0f + *eps;

    float4 xv = *reinterpret_cast<const float4*>(x + (size_t)warp * F_IN + lane * 4);
    float4 a0, a1, a2, a3;
    a0.x = xv.x * s; a0.y = xv.y * s; a0.z = xv.z * s; a0.w = xv.w * s;
    a1 = make_float4(0.f, 0.f, 0.f, 0.f);
    a2 = make_float4(0.f, 0.f, 0.f, 0.f);
    a3 = make_float4(0.f, 0.f, 0.f, 0.f);

    const uint4* xs = reinterpret_cast<const uint4*>(g_xs);

    for (int b = 0; b < deg; b += 32) {
        const int n = min(32, deg - b);
        int idx = (b + lane < deg) ? g_bucket[base + b + lane] : 0;
        int j = 0;
        for (; j + 3 < n; j += 4) {
            int s0 = __shfl_sync(0xffffffff, idx, j);
            int s1 = __shfl_sync(0xffffffff, idx, j + 1);
            int s2 = __shfl_sync(0xffffffff, idx, j + 2);
            int s3 = __shfl_sync(0xffffffff, idx, j + 3);
            uint4 v0 = xs[s0 * 32 + lane];
            uint4 v1 = xs[s1 * 32 + lane];
            uint4 v2 = xs[s2 * 32 + lane];
            uint4 v3 = xs[s3 * 32 + lane];
            {
                float2 h01 = unpack_bf2(v0.x), h23 = unpack_bf2(v0.y);
                float2 l01 = unpack_bf2(v0.z), l23 = unpack_bf2(v0.w);
                a0.x += h01.x + l01.x; a0.y += h01.y + l01.y;
                a0.z += h23.x + l23.x; a0.w += h23.y + l23.y;
            }
            {
                float2 h01 = unpack_bf2(v1.x), h23 = unpack_bf2(v1.y);
                float2 l01 = unpack_bf2(v1.z), l23 = unpack_bf2(v1.w);
                a1.x += h01.x + l01.x; a1.y += h01.y + l01.y;
                a1.z += h23.x + l23.x; a1.w += h23.y + l23.y;
            }
            {
                float2 h01 = unpack_bf2(v2.x), h23 = unpack_bf2(v2.y);
                float2 l01 = unpack_bf2(v2.z), l23 = unpack_bf2(v2.w);
                a2.x += h01.x + l01.x; a2.y += h01.y + l01.y;
                a2.z += h23.x + l23.x; a2.w += h23.y + l23.y;
            }
            {
                float2 h01 = unpack_bf2(v3.x), h23 = unpack_bf2(v3.y);
                float2 l01 = unpack_bf2(v3.z), l23 = unpack_bf2(v3.w);
                a3.x += h01.x + l01.x; a3.y += h01.y + l01.y;
                a3.z += h23.x + l23.x; a3.w += h23.y + l23.y;
            }
        }
        for (; j < n; j++) {
            int s0 = __shfl_sync(0xffffffff, idx, j);
            uint4 v0 = xs[s0 * 32 + lane];
            float2 h01 = unpack_bf2(v0.x), h23 = unpack_bf2(v0.y);
            float2 l01 = unpack_bf2(v0.z), l23 = unpack_bf2(v0.w);
            a0.x += h01.x + l01.x; a0.y += h01.y + l01.y;
            a0.z += h23.x + l23.x; a0.w += h23.y + l23.y;
        }
    }
    a0.x += a1.x + a2.x + a3.x;
    a0.y += a1.y + a2.y + a3.y;
    a0.z += a1.z + a2.z + a3.z;
    a0.w += a1.w + a2.w + a3.w;

    __nv_bfloat16 h0b = __float2bfloat16(a0.x);
    __nv_bfloat16 h1b = __float2bfloat16(a0.y);
    __nv_bfloat16 h2b = __float2bfloat16(a0.z);
    __nv_bfloat16 h3b = __float2bfloat16(a0.w);
    uint2 hv, lv;
    hv.x = pack_bf2(h0b, h1b);
    hv.y = pack_bf2(h2b, h3b);
    lv.x = pack_bf2(__float2bfloat16(a0.x - __bfloat162float(h0b)),
                    __float2bfloat16(a0.y - __bfloat162float(h1b)));
    lv.y = pack_bf2(__float2bfloat16(a0.z - __bfloat162float(h2b)),
                    __float2bfloat16(a0.w - __bfloat162float(h3b)));
    *reinterpret_cast<uint2*>(h_hi + (size_t)warp * F_IN + lane * 4) = hv;
    *reinterpret_cast<uint2*>(h_lo + (size_t)warp * F_IN + lane * 4) = lv;
}

// ---------------------------------------------------------------------------
// Kernel F: overflow fixup (single warp, serial; empty in practice).
// ---------------------------------------------------------------------------
__global__ void fixup_kernel(const float* __restrict__ x,
                             __nv_bfloat16* __restrict__ h_hi,
                             __nv_bfloat16* __restrict__ h_lo)
{
    const int cnt = min(g_ovf_cnt, MAX_OVF);
    const int lane = threadIdx.x;
    for (int e = 0; e < cnt; e++) {
        int s = g_ovf[2 * e];
        int d = g_ovf[2 * e + 1];
        float4 xv = *reinterpret_cast<const float4*>(x + (size_t)s * F_IN + lane * 4);
        uint2 hv = *reinterpret_cast<uint2*>(h_hi + (size_t)d * F_IN + lane * 4);
        uint2 lv = *reinterpret_cast<uint2*>(h_lo + (size_t)d * F_IN + lane * 4);
        float2 h01 = unpack_bf2(hv.x), h23 = unpack_bf2(hv.y);
        float2 l01 = unpack_bf2(lv.x), l23 = unpack_bf2(lv.y);
        float f0 = h01.x + l01.x + xv.x;
        float f1 = h01.y + l01.y + xv.y;
        float f2 = h23.x + l23.x + xv.z;
        float f3 = h23.y + l23.y + xv.w;
        __nv_bfloat16 n0 = __float2bfloat16(f0);
        __nv_bfloat16 n1 = __float2bfloat16(f1);
        __nv_bfloat16 n2 = __float2bfloat16(f2);
        __nv_bfloat16 n3 = __float2bfloat16(f3);
        hv.x = pack_bf2(n0, n1);
        hv.y = pack_bf2(n2, n3);
        lv.x = pack_bf2(__float2bfloat16(f0 - __bfloat162float(n0)),
                        __float2bfloat16(f1 - __bfloat162float(n1)));
        lv.y = pack_bf2(__float2bfloat16(f2 - __bfloat162float(n2)),
                        __float2bfloat16(f3 - __bfloat162float(n3)));
        *reinterpret_cast<uint2*>(h_hi + (size_t)d * F_IN + lane * 4) = hv;
        *reinterpret_cast<uint2*>(h_lo + (size_t)d * F_IN + lane * 4) = lv;
        __syncwarp();
    }
}

// ---------------------------------------------------------------------------
// Fused MLP with cp.async double-buffered weights (unchanged from R11).
// ---------------------------------------------------------------------------
__global__ __launch_bounds__(256, 1)
void fused_mlp_kernel(const __nv_bfloat16* __restrict__ A_hi,
                      const __nv_bfloat16* __restrict__ A_lo,
                      const __nv_bfloat16* __restrict__ W1t_hi,
                      const __nv_bfloat16* __restrict__ W1t_lo,
                      const float* __restrict__ b1,
                      const __nv_bfloat16* __restrict__ W2t_hi,
                      const __nv_bfloat16* __restrict__ W2t_lo,
                      const float* __restrict__ b2,
                      float* __restrict__ out,
                      int M)
{
    constexpr int SM_A_HI  = 0;
    constexpr int SM_A_LO  = 32768;
    constexpr int SM_H_HI  = 65536;
    constexpr int SM_H_LO  = 81920;
    constexpr int SM_W1_HI = 98304;
    constexpr int SM_W1_LO = 98304 + 16384;
    constexpr int SM_W2_HI = 131072;
    constexpr int SM_W2_LO = 131072 + 16384;

    extern __shared__ __align__(1024) char smem[];
    const uint32_t sbase = smem_to_u32(smem);

    const int tid  = threadIdx.x;
    const int wid  = tid >> 5;
    const int lane = tid & 31;
    const int bm   = blockIdx.x * 128;

    const int wm1 = wid >> 1;
    const int wn1 = wid & 1;
    const int wm2 = wid >> 2;
    const int wn2 = wid & 3;

    const int a_row = lane & 15;
    const int a_kh  = (lane >> 4) & 1;
    const int b_row = lane & 7;
    const int b_kh  = (lane >> 3) & 1;
    const int er    = lane >> 2;
    const int ec    = (lane & 3) * 2;

    {
        #pragma unroll
        for (int it = 0; it < 4; it++) {
            int slot = tid + it * 256;
            int r  = slot >> 4;
            int c8 = slot & 15;
            uint32_t off = t64r(r, c8 * 8);
            CP_ASYNC16(sbase + SM_W1_HI + off, W1t_hi + (size_t)r * F_IN + c8 * 8);
            CP_ASYNC16(sbase + SM_W1_LO + off, W1t_lo + (size_t)r * F_IN + c8 * 8);
        }
        CP_COMMIT();
    }

    #pragma unroll
    for (int it = 0; it < 8; it++) {
        int slot = tid + it * 256;
        int r  = slot >> 4;
        int c8 = slot & 15;
        int gr = bm + r;
        uint4 hv, lv;
        if (gr < M) {
            hv = *reinterpret_cast<const uint4*>(A_hi + (size_t)gr * F_IN + c8 * 8);
            lv = *reinterpret_cast<const uint4*>(A_lo + (size_t)gr * F_IN + c8 * 8);
        } else {
            hv = make_uint4(0, 0, 0, 0); lv = make_uint4(0, 0, 0, 0);
        }
        uint32_t off = toff128(r, c8 * 8);
        *reinterpret_cast<uint4*>(smem + SM_A_HI + off) = hv;
        *reinterpret_cast<uint4*>(smem + SM_A_LO + off) = lv;
    }

    float acc_out[4][4][4];
    #pragma unroll
    for (int i = 0; i < 4; i++)
        #pragma unroll
        for (int j = 0; j < 4; j++)
            #pragma unroll
            for (int q = 0; q < 4; q++)
                acc_out[i][j][q] = 0.f;

    for (int c = 0; c < 8; c++) {
        __syncthreads();

        #pragma unroll
        for (int it = 0; it < 4; it++) {
            int slot = tid + it * 256;
            int r  = slot >> 3;
            int c8 = slot & 7;
            uint32_t off = t64c(r, c8 * 8);
            const size_t g = (size_t)r * F_HID + c * 64 + c8 * 8;
            CP_ASYNC16(sbase + SM_W2_HI + off, W2t_hi + g);
            CP_ASYNC16(sbase + SM_W2_LO + off, W2t_lo + g);
        }
        CP_COMMIT();
        CP_WAIT1();
        __syncthreads();

        float acc_h[2][4][4];
        #pragma unroll
        for (int i = 0; i < 2; i++)
            #pragma unroll
            for (int j = 0; j < 4; j++)
                #pragma unroll
                for (int q = 0; q < 4; q++)
                    acc_h[i][j][q] = 0.f;

        #pragma unroll
        for (int ks = 0; ks < 8; ks++) {
            uint32_t bh[4][2], bl[4][2];
            #pragma unroll
            for (int nt = 0; nt < 4; nt++) {
                int n = wn1 * 32 + nt * 8 + b_row;
                uint32_t off = t64r(n, ks * 16 + b_kh * 8);
                ldmx2(bh[nt], sbase + SM_W1_HI + off);
                ldmx2(bl[nt], sbase + SM_W1_LO + off);
            }
            #pragma unroll
            for (int mt = 0; mt < 2; mt++) {
                int m = wm1 * 32 + mt * 16 + a_row;
                uint32_t off = toff128(m, ks * 16 + a_kh * 8);
                uint32_t ah[4], al[4];
                ldmx4(ah, sbase + SM_A_HI + off);
                ldmx4(al, sbase + SM_A_LO + off);
                #pragma unroll
                for (int nt = 0; nt < 4; nt++) {
                    mma16816(acc_h[mt][nt], ah, bh[nt]);
                    mma16816(acc_h[mt][nt], ah, bl[nt]);
                    mma16816(acc_h[mt][nt], al, bh[nt]);
                }
            }
        }
        __syncthreads();

        if (c + 1 < 8) {
            #pragma unroll
            for (int it = 0; it < 4; it++) {
                int slot = tid + it * 256;
                int r  = slot >> 4;
                int c8 = slot & 15;
                uint32_t off = t64r(r, c8 * 8);
                const size_t g = (size_t)((c + 1) * 64 + r) * F_IN + c8 * 8;
                CP_ASYNC16(sbase + SM_W1_HI + off, W1t_hi + g);
                CP_ASYNC16(sbase + SM_W1_LO + off, W1t_lo + g);
            }
        }
        CP_COMMIT();

        #pragma unroll
        for (int mt = 0; mt < 2; mt++) {
            int lr0 = wm1 * 32 + mt * 16 + er;
            #pragma unroll
            for (int nt = 0; nt < 4; nt++) {
                int lc = wn1 * 32 + nt * 8 + ec;
                float bia0 = b1[c * 64 + lc];
                float bia1 = b1[c * 64 + lc + 1];
                #pragma unroll
                for (int h = 0; h < 2; h++) {
                    float v0 = fmaxf(acc_h[mt][nt][2 * h + 0] + bia0, 0.f);
                    float v1 = fmaxf(acc_h[mt][nt][2 * h + 1] + bia1, 0.f);
                    __nv_bfloat16 hh0 = __float2bfloat16(v0);
                    __nv_bfloat16 hh1 = __float2bfloat16(v1);
                    uint32_t off = t64c(lr0 + h * 8, lc);
                    *reinterpret_cast<uint32_t*>(smem + SM_H_HI + off) = pack_bf2(hh0, hh1);
                    *reinterpret_cast<uint32_t*>(smem + SM_H_LO + off) =
                        pack_bf2(__float2bfloat16(v0 - __bfloat162float(hh0)),
                                 __float2bfloat16(v1 - __bfloat162float(hh1)));
                }
            }
        }
        CP_WAIT1();
        __syncthreads();

        #pragma unroll
        for (int ks = 0; ks < 4; ks++) {
            uint32_t bh[4][2], bl[4][2];
            #pragma unroll
            for (int nt = 0; nt < 4; nt++) {
                int n = wn2 * 32 + nt * 8 + b_row;
                uint32_t off = t64c(n, ks * 16 + b_kh * 8);
                ldmx2(bh[nt], sbase + SM_W2_HI + off);
                ldmx2(bl[nt], sbase + SM_W2_LO + off);
            }
            #pragma unroll
            for (int mt = 0; mt < 4; mt++) {
                int m = wm2 * 64 + mt * 16 + a_row;
                uint32_t off = t64c(m, ks * 16 + a_kh * 8);
                uint32_t ah[4], al[4];
                ldmx4(ah, sbase + SM_H_HI + off);
                ldmx4(al, sbase + SM_H_LO + off);
                #pragma unroll
                for (int nt = 0; nt < 4; nt++) {
                    mma16816(acc_out[mt][nt], ah, bh[nt]);
                    mma16816(acc_out[mt][nt], ah, bl[nt]);
                    mma16816(acc_out[mt][nt], al, bh[nt]);
                }
            }
        }
    }

    #pragma unroll
    for (int mt = 0; mt < 4; mt++) {
        const int row0 = bm + wm2 * 64 + mt * 16 + er;
        #pragma unroll
        for (int nt = 0; nt < 4; nt++) {
            const int col = wn2 * 32 + nt * 8 + ec;
            const float bia0 = b2[col], bia1 = b2[col + 1];
            #pragma unroll
            for (int h = 0; h < 2; h++) {
                const int row = row0 + h * 8;
                if (row >= M) continue;
                float2 v;
                v.x = acc_out[mt][nt][2 * h + 0] + bia0;
                v.y = acc_out[mt][nt][2 * h + 1] + bia1;
                *reinterpret_cast<float2*>(out + (size_t)row * F_IN + col) = v;
            }
        }
    }
}

// ---------------------------------------------------------------------------
// Launch
// ---------------------------------------------------------------------------
extern "C" void kernel_launch(void* const* d_in, const int* in_sizes, int n_in,
                              void* d_out, int out_size)
{
    const float* x   = (const float*)d_in[0];
    const void*  ei  = d_in[1];
    const float* W1  = (const float*)d_in[2];
    const float* b1  = (const float*)d_in[3];
    const float* W2  = (const float*)d_in[4];
    const float* b2  = (const float*)d_in[5];
    const float* eps = (const float*)d_in[6];
    float* out = (float*)d_out;

    const int n_edges = in_sizes[1] / 2;

    __nv_bfloat16 *h0hi, *h0lo, *w1th, *w1tl, *w2th, *w2tl;
    cudaGetSymbolAddress((void**)&h0hi, g_h0_hi);
    cudaGetSymbolAddress((void**)&h0lo, g_h0_lo);
    cudaGetSymbolAddress((void**)&w1th, g_w1t_hi);
    cudaGetSymbolAddress((void**)&w1tl, g_w1t_lo);
    cudaGetSymbolAddress((void**)&w2th, g_w2t_hi);
    cudaGetSymbolAddress((void**)&w2tl, g_w2t_lo);

    // 0) zero counters + dtype detect; x split; weight prep
    zero_kernel<<<(N_NODES + 255) / 256, 256>>>((const int*)ei);
    splitx_kernel<<<(N_NODES * 32 + 255) / 256, 256>>>(x);
    transpose_split_kernel<<<(F_IN * F_HID + 255) / 256, 256>>>(W1, F_IN, F_HID, w1th, w1tl);
    transpose_split_kernel<<<(F_HID * F_IN + 255) / 256, 256>>>(W2, F_HID, F_IN, w2th, w2tl);

    // 1) single-pass fixed-capacity bucketing
    bucket_kernel<<<(n_edges + 2047) / 2048, 256>>>(ei, n_edges);

    // 2) gather-accumulate -> split bf16 h0; then (empty) overflow fixup
    {
        const int wpb = 8;
        gather_kernel<<<(N_NODES + wpb - 1) / wpb, wpb * 32>>>(x, eps, h0hi, h0lo);
        fixup_kernel<<<1, 32>>>(x, h0hi, h0lo);
    }

    // 3) fused MLP (cp.async double-buffered weights)
    {
        constexpr int SMEM = 163840;   // 160 KB
        cudaFuncSetAttribute(fused_mlp_kernel,
                             cudaFuncAttributeMaxDynamicSharedMemorySize, SMEM);
        const int mtiles = (N_NODES + 127) / 128;   // 391
        fused_mlp_kernel<<<mtiles, 256, SMEM>>>(
            h0hi, h0lo, w1th, w1tl, b1, w2th, w2tl, b2, out, N_NODES);
    }
}

// round 13
// speedup vs baseline: 1.0934x; 1.0934x over previous
#include <cuda_runtime.h>
#include <cuda_bf16.h>
#include <cstdint>

#define N_NODES 50000
#define F_IN    128
#define F_HID   512
#define CAP     128            // fixed bucket capacity per node
#define MAX_OVF 4096           // overflow list capacity (never used in practice)

// ---------------------------------------------------------------------------
// Scratch (__device__ globals; allocation-free rule)
// ---------------------------------------------------------------------------
__device__ __align__(16) __nv_bfloat16 g_h0_hi[N_NODES * F_IN];       // split h0
__device__ __align__(16) __nv_bfloat16 g_h0_lo[N_NODES * F_IN];
__device__ __align__(16) __nv_bfloat16 g_w1t_hi[F_HID * F_IN];        // W1^T split [512,128]
__device__ __align__(16) __nv_bfloat16 g_w1t_lo[F_HID * F_IN];
__device__ __align__(16) __nv_bfloat16 g_w2t_hi[F_IN * F_HID];        // W2^T split [128,512]
__device__ __align__(16) __nv_bfloat16 g_w2t_lo[F_IN * F_HID];
__device__ int g_cur[N_NODES];                 // per-node fill counters (=degree)
__device__ int g_bucket[N_NODES * CAP];        // fixed-capacity buckets of src ids
__device__ int g_ovf[2 * MAX_OVF];             // overflow (src,dst) pairs
__device__ int g_ovf_cnt;
__device__ int g_idx_is64;

__device__ __forceinline__ uint32_t smem_to_u32(const void* p) {
    uint32_t a;
    asm("{ .reg .u64 t; cvta.to.shared.u64 t, %1; cvt.u32.u64 %0, t; }"
        : "=r"(a) : "l"(p));
    return a;
}
__device__ __forceinline__ uint32_t pack_bf2(__nv_bfloat16 a, __nv_bfloat16 b) {
    __nv_bfloat162 t(a, b);
    return *reinterpret_cast<uint32_t*>(&t);
}
__device__ __forceinline__ float2 unpack_bf2(uint32_t w) {
    __nv_bfloat162 t = *reinterpret_cast<__nv_bfloat162*>(&w);
    return __bfloat1622float2(t);
}
__device__ __forceinline__ uint32_t sw128(uint32_t byte_off) {
    return byte_off ^ ((byte_off >> 3) & 0x70);
}
// 64x128 bf16 tile (A tile, W1 chunk): two 64x64 column blocks (8KB each)
__device__ __forceinline__ uint32_t t64r(int r, int k) {
    return (uint32_t)((k >> 6) * 8192) + sw128((uint32_t)(r * 128 + (k & 63) * 2));
}
// Nx64 bf16 tile (H: 64 rows; W2 chunk: 128 rows): single block, 128B rows
__device__ __forceinline__ uint32_t t64c(int r, int k) {
    return sw128((uint32_t)(r * 128 + k * 2));
}

__device__ __forceinline__ void ldmx4(uint32_t* r, uint32_t addr) {
    asm volatile("ldmatrix.sync.aligned.m8n8.x4.shared.b16 {%0,%1,%2,%3}, [%4];"
                 : "=r"(r[0]), "=r"(r[1]), "=r"(r[2]), "=r"(r[3]) : "r"(addr));
}
__device__ __forceinline__ void ldmx2(uint32_t* r, uint32_t addr) {
    asm volatile("ldmatrix.sync.aligned.m8n8.x2.shared.b16 {%0,%1}, [%2];"
                 : "=r"(r[0]), "=r"(r[1]) : "r"(addr));
}
__device__ __forceinline__ void mma16816(float* c, const uint32_t* a, const uint32_t* b) {
    asm volatile(
        "mma.sync.aligned.m16n8k16.row.col.f32.bf16.bf16.f32 "
        "{%0,%1,%2,%3}, {%4,%5,%6,%7}, {%8,%9}, {%0,%1,%2,%3};"
        : "+f"(c[0]), "+f"(c[1]), "+f"(c[2]), "+f"(c[3])
        : "r"(a[0]), "r"(a[1]), "r"(a[2]), "r"(a[3]), "r"(b[0]), "r"(b[1]));
}
#define CP_ASYNC16(dst_u32, src_ptr) \
    asm volatile("cp.async.cg.shared.global [%0], [%1], 16;" \
                 :: "r"(dst_u32), "l"(src_ptr) : "memory")
#define CP_COMMIT() asm volatile("cp.async.commit_group;" ::: "memory")
#define CP_WAIT1()  asm volatile("cp.async.wait_group 1;"  ::: "memory")

__device__ __forceinline__ int load_idx(const void* ei, int i) {
    return g_idx_is64 ? (int)((const long long*)ei)[i] : ((const int*)ei)[i];
}

// ---------------------------------------------------------------------------
// Kernel A: zero bucket counters + overflow counter + dtype detection
// ---------------------------------------------------------------------------
__global__ void zero_kernel(const int* __restrict__ ei_words)
{
    int i = blockIdx.x * blockDim.x + threadIdx.x;
    if (i < N_NODES) g_cur[i] = 0;
    if (i == 0) {
        g_ovf_cnt = 0;
        int is64 = 1;
        #pragma unroll
        for (int k = 0; k < 64; k++) {
            if (ei_words[2 * k + 1] != 0) { is64 = 0; break; }
        }
        g_idx_is64 = is64;
    }
}

// ---------------------------------------------------------------------------
// Kernel B: single-pass bucketing (atomicAdd doubles as histogram), 4/thread.
// ---------------------------------------------------------------------------
__global__ void bucket_kernel(const void* __restrict__ ei, int n_edges)
{
    int base = blockIdx.x * 1024;
    #pragma unroll
    for (int k = 0; k < 4; k++) {
        int e = base + k * 256 + threadIdx.x;
        if (e < n_edges) {
            int s = load_idx(ei, e);
            int d = load_idx(ei, n_edges + e);
            if (s >= 0 && s < N_NODES && d >= 0 && d < N_NODES) {
                int pos = atomicAdd(&g_cur[d], 1);
                if (pos < CAP) {
                    g_bucket[d * CAP + pos] = s;
                } else {
                    int o = atomicAdd(&g_ovf_cnt, 1);
                    if (o < MAX_OVF) {
                        g_ovf[2 * o] = s;
                        g_ovf[2 * o + 1] = d;
                    }
                }
            }
        }
    }
}

// ---------------------------------------------------------------------------
// Kernel: weight transpose + hi/lo bf16 split. out[n*K+k] = split(W[k*N+n]).
// ---------------------------------------------------------------------------
__global__ void transpose_split_kernel(const float* __restrict__ W, int K, int N,
                                       __nv_bfloat16* __restrict__ out_hi,
                                       __nv_bfloat16* __restrict__ out_lo)
{
    int idx = blockIdx.x * blockDim.x + threadIdx.x;
    if (idx >= K * N) return;
    int n = idx / K, k = idx % K;
    float v = W[(size_t)k * N + n];
    __nv_bfloat16 h = __float2bfloat16(v);
    out_hi[idx] = h;
    out_lo[idx] = __float2bfloat16(v - __bfloat162float(h));
}

// ---------------------------------------------------------------------------
// Kernel E: gather-accumulate, warp per node, lane-parallel index loads.
// (R11 version — fp32 x reads)
// ---------------------------------------------------------------------------
__global__ __launch_bounds__(256)
void gather_kernel(const float* __restrict__ x,
                   const float* __restrict__ eps,
                   __nv_bfloat16* __restrict__ h_hi,
                   __nv_bfloat16* __restrict__ h_lo)
{
    const int warp = (blockIdx.x * blockDim.x + threadIdx.x) >> 5;
    if (warp >= N_NODES) return;
    const int lane = threadIdx.x & 31;

    const int deg  = min(g_cur[warp], CAP);
    const int base = warp * CAP;
    const float s = 1.0f + *eps;

    float4 xv = *reinterpret_cast<const float4*>(x + (size_t)warp * F_IN + lane * 4);
    float4 a0, a1, a2, a3;
    a0.x = xv.x * s; a0.y = xv.y * s; a0.z = xv.z * s; a0.w = xv.w * s;
    a1 = make_float4(0.f, 0.f, 0.f, 0.f);
    a2 = make_float4(0.f, 0.f, 0.f, 0.f);
    a3 = make_float4(0.f, 0.f, 0.f, 0.f);

    for (int b = 0; b < deg; b += 32) {
        const int n = min(32, deg - b);
        int idx = (b + lane < deg) ? g_bucket[base + b + lane] : 0;
        int j = 0;
        for (; j + 3 < n; j += 4) {
            int s0 = __shfl_sync(0xffffffff, idx, j);
            int s1 = __shfl_sync(0xffffffff, idx, j + 1);
            int s2 = __shfl_sync(0xffffffff, idx, j + 2);
            int s3 = __shfl_sync(0xffffffff, idx, j + 3);
            float4 v0 = *reinterpret_cast<const float4*>(x + (size_t)s0 * F_IN + lane * 4);
            float4 v1 = *reinterpret_cast<const float4*>(x + (size_t)s1 * F_IN + lane * 4);
            float4 v2 = *reinterpret_cast<const float4*>(x + (size_t)s2 * F_IN + lane * 4);
            float4 v3 = *reinterpret_cast<const float4*>(x + (size_t)s3 * F_IN + lane * 4);
            a0.x += v0.x; a0.y += v0.y; a0.z += v0.z; a0.w += v0.w;
            a1.x += v1.x; a1.y += v1.y; a1.z += v1.z; a1.w += v1.w;
            a2.x += v2.x; a2.y += v2.y; a2.z += v2.z; a2.w += v2.w;
            a3.x += v3.x; a3.y += v3.y; a3.z += v3.z; a3.w += v3.w;
        }
        for (; j < n; j++) {
            int s0 = __shfl_sync(0xffffffff, idx, j);
            float4 v0 = *reinterpret_cast<const float4*>(x + (size_t)s0 * F_IN + lane * 4);
            a0.x += v0.x; a0.y += v0.y; a0.z += v0.z; a0.w += v0.w;
        }
    }
    a0.x += a1.x + a2.x + a3.x;
    a0.y += a1.y + a2.y + a3.y;
    a0.z += a1.z + a2.z + a3.z;
    a0.w += a1.w + a2.w + a3.w;

    __nv_bfloat16 h0b = __float2bfloat16(a0.x);
    __nv_bfloat16 h1b = __float2bfloat16(a0.y);
    __nv_bfloat16 h2b = __float2bfloat16(a0.z);
    __nv_bfloat16 h3b = __float2bfloat16(a0.w);
    uint2 hv, lv;
    hv.x = pack_bf2(h0b, h1b);
    hv.y = pack_bf2(h2b, h3b);
    lv.x = pack_bf2(__float2bfloat16(a0.x - __bfloat162float(h0b)),
                    __float2bfloat16(a0.y - __bfloat162float(h1b)));
    lv.y = pack_bf2(__float2bfloat16(a0.z - __bfloat162float(h2b)),
                    __float2bfloat16(a0.w - __bfloat162float(h3b)));
    *reinterpret_cast<uint2*>(h_hi + (size_t)warp * F_IN + lane * 4) = hv;
    *reinterpret_cast<uint2*>(h_lo + (size_t)warp * F_IN + lane * 4) = lv;
}

// ---------------------------------------------------------------------------
// Kernel F: overflow fixup (single warp, serial; empty in practice).
// ---------------------------------------------------------------------------
__global__ void fixup_kernel(const float* __restrict__ x,
                             __nv_bfloat16* __restrict__ h_hi,
                             __nv_bfloat16* __restrict__ h_lo)
{
    const int cnt = min(g_ovf_cnt, MAX_OVF);
    const int lane = threadIdx.x;
    for (int e = 0; e < cnt; e++) {
        int s = g_ovf[2 * e];
        int d = g_ovf[2 * e + 1];
        float4 xv = *reinterpret_cast<const float4*>(x + (size_t)s * F_IN + lane * 4);
        uint2 hv = *reinterpret_cast<uint2*>(h_hi + (size_t)d * F_IN + lane * 4);
        uint2 lv = *reinterpret_cast<uint2*>(h_lo + (size_t)d * F_IN + lane * 4);
        float2 h01 = unpack_bf2(hv.x), h23 = unpack_bf2(hv.y);
        float2 l01 = unpack_bf2(lv.x), l23 = unpack_bf2(lv.y);
        float f0 = h01.x + l01.x + xv.x;
        float f1 = h01.y + l01.y + xv.y;
        float f2 = h23.x + l23.x + xv.z;
        float f3 = h23.y + l23.y + xv.w;
        __nv_bfloat16 n0 = __float2bfloat16(f0);
        __nv_bfloat16 n1 = __float2bfloat16(f1);
        __nv_bfloat16 n2 = __float2bfloat16(f2);
        __nv_bfloat16 n3 = __float2bfloat16(f3);
        hv.x = pack_bf2(n0, n1);
        hv.y = pack_bf2(n2, n3);
        lv.x = pack_bf2(__float2bfloat16(f0 - __bfloat162float(n0)),
                        __float2bfloat16(f1 - __bfloat162float(n1)));
        lv.y = pack_bf2(__float2bfloat16(f2 - __bfloat162float(n2)),
                        __float2bfloat16(f3 - __bfloat162float(n3)));
        *reinterpret_cast<uint2*>(h_hi + (size_t)d * F_IN + lane * 4) = hv;
        *reinterpret_cast<uint2*>(h_lo + (size_t)d * F_IN + lane * 4) = lv;
        __syncwarp();
    }
}

// ---------------------------------------------------------------------------
// Fused MLP, BM=64, occupancy 2. cp.async double-buffered weights.
// SMEM (112KB): A(32K, 64x128) | H(16K, 64x64) | W1(32K, 64x128) | W2(32K, 128x64)
// 8 hidden-chunks of 64. GEMM1 out 64x64 (warp 32x16); GEMM2 out 64x128 (warp 32x32).
// ---------------------------------------------------------------------------
__global__ __launch_bounds__(256, 2)
void fused_mlp_kernel(const __nv_bfloat16* __restrict__ A_hi,
                      const __nv_bfloat16* __restrict__ A_lo,
                      const __nv_bfloat16* __restrict__ W1t_hi,
                      const __nv_bfloat16* __restrict__ W1t_lo,
                      const float* __restrict__ b1,
                      const __nv_bfloat16* __restrict__ W2t_hi,
                      const __nv_bfloat16* __restrict__ W2t_lo,
                      const float* __restrict__ b2,
                      float* __restrict__ out,
                      int M)
{
    constexpr int SM_A_HI  = 0;          // 16KB (64x128, t64r)
    constexpr int SM_A_LO  = 16384;
    constexpr int SM_H_HI  = 32768;      // 8KB (64x64, t64c)
    constexpr int SM_H_LO  = 40960;
    constexpr int SM_W1_HI = 49152;      // 16KB (64x128, t64r)
    constexpr int SM_W1_LO = 65536;
    constexpr int SM_W2_HI = 81920;      // 16KB (128x64, t64c)
    constexpr int SM_W2_LO = 98304;

    extern __shared__ __align__(1024) char smem[];
    const uint32_t sbase = smem_to_u32(smem);

    const int tid  = threadIdx.x;
    const int wid  = tid >> 5;
    const int lane = tid & 31;
    const int bm   = blockIdx.x * 64;

    // GEMM1 warps: 2m x 4n (warp tile 32x16); GEMM2 warps: 2m x 4n (32x32)
    const int wm = wid >> 2;            // 0..1
    const int wn = wid & 3;             // 0..3

    const int a_row = lane & 15;
    const int a_kh  = (lane >> 4) & 1;
    const int b_row = lane & 7;
    const int b_kh  = (lane >> 3) & 1;
    const int er    = lane >> 2;
    const int ec    = (lane & 3) * 2;

    // ---- preload W1 chunk 0 (64x128) via cp.async ----
    {
        #pragma unroll
        for (int it = 0; it < 4; it++) {
            int slot = tid + it * 256;      // 1024 slots: 64 rows x 16 uint4
            int r  = slot >> 4;
            int c8 = slot & 15;
            uint32_t off = t64r(r, c8 * 8);
            CP_ASYNC16(sbase + SM_W1_HI + off, W1t_hi + (size_t)r * F_IN + c8 * 8);
            CP_ASYNC16(sbase + SM_W1_LO + off, W1t_lo + (size_t)r * F_IN + c8 * 8);
        }
        CP_COMMIT();
    }

    // ---- stage A = pre-split h0 block [64 x 128] ----
    #pragma unroll
    for (int it = 0; it < 4; it++) {
        int slot = tid + it * 256;          // 1024 uint4 slots
        int r  = slot >> 4;                 // 16 uint4 per row
        int c8 = slot & 15;
        int gr = bm + r;
        uint4 hv, lv;
        if (gr < M) {
            hv = *reinterpret_cast<const uint4*>(A_hi + (size_t)gr * F_IN + c8 * 8);
            lv = *reinterpret_cast<const uint4*>(A_lo + (size_t)gr * F_IN + c8 * 8);
        } else {
            hv = make_uint4(0, 0, 0, 0); lv = make_uint4(0, 0, 0, 0);
        }
        uint32_t off = t64r(r, c8 * 8);
        *reinterpret_cast<uint4*>(smem + SM_A_HI + off) = hv;
        *reinterpret_cast<uint4*>(smem + SM_A_LO + off) = lv;
    }

    float acc_out[2][4][4];
    #pragma unroll
    for (int i = 0; i < 2; i++)
        #pragma unroll
        for (int j = 0; j < 4; j++)
            #pragma unroll
            for (int q = 0; q < 4; q++)
                acc_out[i][j][q] = 0.f;

    for (int c = 0; c < 8; c++) {           // 8 hidden chunks of 64
        __syncthreads();                    // GEMM2(c-1) readers done (W2 buf, H)

        // stream W2[c]: 128 rows x 64 k
        #pragma unroll
        for (int it = 0; it < 4; it++) {
            int slot = tid + it * 256;      // 1024 slots: 128 rows x 8 uint4
            int r  = slot >> 3;
            int c8 = slot & 7;
            uint32_t off = t64c(r, c8 * 8);
            const size_t g = (size_t)r * F_HID + c * 64 + c8 * 8;
            CP_ASYNC16(sbase + SM_W2_HI + off, W2t_hi + g);
            CP_ASYNC16(sbase + SM_W2_LO + off, W2t_lo + g);
        }
        CP_COMMIT();
        CP_WAIT1();                         // W1[c] arrived
        __syncthreads();                    // publish W1[c]

        // ---- GEMM1: H = A @ W1c  (out 64x64, K=128), warp tile 32x16 ----
        float acc_h[2][2][4];
        #pragma unroll
        for (int i = 0; i < 2; i++)
            #pragma unroll
            for (int j = 0; j < 2; j++)
                #pragma unroll
                for (int q = 0; q < 4; q++)
                    acc_h[i][j][q] = 0.f;

        #pragma unroll
        for (int ks = 0; ks < 8; ks++) {
            uint32_t bh[2][2], bl[2][2];
            #pragma unroll
            for (int nt = 0; nt < 2; nt++) {
                int n = wn * 16 + nt * 8 + b_row;
                uint32_t off = t64r(n, ks * 16 + b_kh * 8);
                ldmx2(bh[nt], sbase + SM_W1_HI + off);
                ldmx2(bl[nt], sbase + SM_W1_LO + off);
            }
            #pragma unroll
            for (int mt = 0; mt < 2; mt++) {
                int m = wm * 32 + mt * 16 + a_row;
                uint32_t off = t64r(m, ks * 16 + a_kh * 8);
                uint32_t ah[4], al[4];
                ldmx4(ah, sbase + SM_A_HI + off);
                ldmx4(al, sbase + SM_A_LO + off);
                #pragma unroll
                for (int nt = 0; nt < 2; nt++) {
                    mma16816(acc_h[mt][nt], ah, bh[nt]);
                    mma16816(acc_h[mt][nt], ah, bl[nt]);
                    mma16816(acc_h[mt][nt], al, bh[nt]);
                }
            }
        }
        __syncthreads();                    // all warps done reading W1 buf

        // prefetch W1[c+1] into the freed W1 buffer
        if (c + 1 < 8) {
            #pragma unroll
            for (int it = 0; it < 4; it++) {
                int slot = tid + it * 256;
                int r  = slot >> 4;
                int c8 = slot & 15;
                uint32_t off = t64r(r, c8 * 8);
                const size_t g = (size_t)((c + 1) * 64 + r) * F_IN + c8 * 8;
                CP_ASYNC16(sbase + SM_W1_HI + off, W1t_hi + g);
                CP_ASYNC16(sbase + SM_W1_LO + off, W1t_lo + g);
            }
        }
        CP_COMMIT();                        // (empty group when c==7)

        // bias + relu + split -> H (64x64)
        #pragma unroll
        for (int mt = 0; mt < 2; mt++) {
            int lr0 = wm * 32 + mt * 16 + er;
            #pragma unroll
            for (int nt = 0; nt < 2; nt++) {
                int lc = wn * 16 + nt * 8 + ec;
                float bia0 = b1[c * 64 + lc];
                float bia1 = b1[c * 64 + lc + 1];
                #pragma unroll
                for (int h = 0; h < 2; h++) {
                    float v0 = fmaxf(acc_h[mt][nt][2 * h + 0] + bia0, 0.f);
                    float v1 = fmaxf(acc_h[mt][nt][2 * h + 1] + bia1, 0.f);
                    __nv_bfloat16 hh0 = __float2bfloat16(v0);
                    __nv_bfloat16 hh1 = __float2bfloat16(v1);
                    uint32_t off = t64c(lr0 + h * 8, lc);
                    *reinterpret_cast<uint32_t*>(smem + SM_H_HI + off) = pack_bf2(hh0, hh1);
                    *reinterpret_cast<uint32_t*>(smem + SM_H_LO + off) =
                        pack_bf2(__float2bfloat16(v0 - __bfloat162float(hh0)),
                                 __float2bfloat16(v1 - __bfloat162float(hh1)));
                }
            }
        }
        CP_WAIT1();                         // W2[c] arrived
        __syncthreads();                    // publish H + W2[c]

        // ---- GEMM2: out += H @ W2c  (out 64x128, K=64), warp tile 32x32 ----
        #pragma unroll
        for (int ks = 0; ks < 4; ks++) {
            uint32_t bh[4][2], bl[4][2];
            #pragma unroll
            for (int nt = 0; nt < 4; nt++) {
                int n = wn * 32 + nt * 8 + b_row;
                uint32_t off = t64c(n, ks * 16 + b_kh * 8);
                ldmx2(bh[nt], sbase + SM_W2_HI + off);
                ldmx2(bl[nt], sbase + SM_W2_LO + off);
            }
            #pragma unroll
            for (int mt = 0; mt < 2; mt++) {
                int m = wm * 32 + mt * 16 + a_row;
                uint32_t off = t64c(m, ks * 16 + a_kh * 8);
                uint32_t ah[4], al[4];
                ldmx4(ah, sbase + SM_H_HI + off);
                ldmx4(al, sbase + SM_H_LO + off);
                #pragma unroll
                for (int nt = 0; nt < 4; nt++) {
                    mma16816(acc_out[mt][nt], ah, bh[nt]);
                    mma16816(acc_out[mt][nt], ah, bl[nt]);
                    mma16816(acc_out[mt][nt], al, bh[nt]);
                }
            }
        }
    }

    // ---- epilogue: out + b2, fp32 ----
    #pragma unroll
    for (int mt = 0; mt < 2; mt++) {
        const int row0 = bm + wm * 32 + mt * 16 + er;
        #pragma unroll
        for (int nt = 0; nt < 4; nt++) {
            const int col = wn * 32 + nt * 8 + ec;
            const float bia0 = b2[col], bia1 = b2[col + 1];
            #pragma unroll
            for (int h = 0; h < 2; h++) {
                const int row = row0 + h * 8;
                if (row >= M) continue;
                float2 v;
                v.x = acc_out[mt][nt][2 * h + 0] + bia0;
                v.y = acc_out[mt][nt][2 * h + 1] + bia1;
                *reinterpret_cast<float2*>(out + (size_t)row * F_IN + col) = v;
            }
        }
    }
}

// ---------------------------------------------------------------------------
// Launch
// ---------------------------------------------------------------------------
extern "C" void kernel_launch(void* const* d_in, const int* in_sizes, int n_in,
                              void* d_out, int out_size)
{
    const float* x   = (const float*)d_in[0];
    const void*  ei  = d_in[1];
    const float* W1  = (const float*)d_in[2];
    const float* b1  = (const float*)d_in[3];
    const float* W2  = (const float*)d_in[4];
    const float* b2  = (const float*)d_in[5];
    const float* eps = (const float*)d_in[6];
    float* out = (float*)d_out;

    const int n_edges = in_sizes[1] / 2;

    __nv_bfloat16 *h0hi, *h0lo, *w1th, *w1tl, *w2th, *w2tl;
    cudaGetSymbolAddress((void**)&h0hi, g_h0_hi);
    cudaGetSymbolAddress((void**)&h0lo, g_h0_lo);
    cudaGetSymbolAddress((void**)&w1th, g_w1t_hi);
    cudaGetSymbolAddress((void**)&w1tl, g_w1t_lo);
    cudaGetSymbolAddress((void**)&w2th, g_w2t_hi);
    cudaGetSymbolAddress((void**)&w2tl, g_w2t_lo);

    // 0) zero counters + dtype detect; weight prep
    zero_kernel<<<(N_NODES + 255) / 256, 256>>>((const int*)ei);
    transpose_split_kernel<<<(F_IN * F_HID + 255) / 256, 256>>>(W1, F_IN, F_HID, w1th, w1tl);
    transpose_split_kernel<<<(F_HID * F_IN + 255) / 256, 256>>>(W2, F_HID, F_IN, w2th, w2tl);

    // 1) single-pass fixed-capacity bucketing
    bucket_kernel<<<(n_edges + 1023) / 1024, 256>>>(ei, n_edges);

    // 2) gather-accumulate -> split bf16 h0; then (empty) overflow fixup
    {
        const int wpb = 8;
        gather_kernel<<<(N_NODES + wpb - 1) / wpb, wpb * 32>>>(x, eps, h0hi, h0lo);
        fixup_kernel<<<1, 32>>>(x, h0hi, h0lo);
    }

    // 3) fused MLP (BM=64, occupancy 2, cp.async double-buffered weights)
    {
        constexpr int SMEM = 114688;   // 112 KB
        cudaFuncSetAttribute(fused_mlp_kernel,
                             cudaFuncAttributeMaxDynamicSharedMemorySize, SMEM);
        const int mtiles = (N_NODES + 63) / 64;   // 782
        fused_mlp_kernel<<<mtiles, 256, SMEM>>>(
            h0hi, h0lo, w1th, w1tl, b1, w2th, w2tl, b2, out, N_NODES);
    }
}

// round 14
// speedup vs baseline: 1.1638x; 1.0644x over previous
#include <cuda_runtime.h>
#include <cuda_bf16.h>
#include <cstdint>

#define N_NODES 50000
#define F_IN    128
#define F_HID   512
#define CAP     128            // fixed bucket capacity per node
#define MAX_OVF 4096           // overflow list capacity (never used in practice)

// ---------------------------------------------------------------------------
// Scratch (__device__ globals; allocation-free rule)
// NOTE self-maintaining invariants: g_cur is zeroed by gather_kernel's tail,
// g_ovf_cnt by fixup_kernel's tail. Initial state is static zero.
// ---------------------------------------------------------------------------
__device__ __align__(16) __nv_bfloat16 g_h0_hi[N_NODES * F_IN];       // split h0
__device__ __align__(16) __nv_bfloat16 g_h0_lo[N_NODES * F_IN];
__device__ __align__(16) __nv_bfloat16 g_w1t_hi[F_HID * F_IN];        // W1^T split [512,128]
__device__ __align__(16) __nv_bfloat16 g_w1t_lo[F_HID * F_IN];
__device__ __align__(16) __nv_bfloat16 g_w2t_hi[F_IN * F_HID];        // W2^T split [128,512]
__device__ __align__(16) __nv_bfloat16 g_w2t_lo[F_IN * F_HID];
__device__ int g_cur[N_NODES];                 // per-node fill counters (=degree)
__device__ int g_bucket[N_NODES * CAP];        // fixed-capacity buckets of src ids
__device__ int g_ovf[2 * MAX_OVF];             // overflow (src,dst) pairs
__device__ int g_ovf_cnt;

__device__ __forceinline__ uint32_t smem_to_u32(const void* p) {
    uint32_t a;
    asm("{ .reg .u64 t; cvta.to.shared.u64 t, %1; cvt.u32.u64 %0, t; }"
        : "=r"(a) : "l"(p));
    return a;
}
__device__ __forceinline__ uint32_t pack_bf2(__nv_bfloat16 a, __nv_bfloat16 b) {
    __nv_bfloat162 t(a, b);
    return *reinterpret_cast<uint32_t*>(&t);
}
__device__ __forceinline__ float2 unpack_bf2(uint32_t w) {
    __nv_bfloat162 t = *reinterpret_cast<__nv_bfloat162*>(&w);
    return __bfloat1622float2(t);
}
__device__ __forceinline__ uint32_t sw128(uint32_t byte_off) {
    return byte_off ^ ((byte_off >> 3) & 0x70);
}
// 64x128 bf16 tile (A tile, W1 chunk): two 64x64 column blocks (8KB each)
__device__ __forceinline__ uint32_t t64r(int r, int k) {
    return (uint32_t)((k >> 6) * 8192) + sw128((uint32_t)(r * 128 + (k & 63) * 2));
}
// Nx64 bf16 tile (H: 64 rows; W2 chunk: 128 rows): single block, 128B rows
__device__ __forceinline__ uint32_t t64c(int r, int k) {
    return sw128((uint32_t)(r * 128 + k * 2));
}

__device__ __forceinline__ void ldmx4(uint32_t* r, uint32_t addr) {
    asm volatile("ldmatrix.sync.aligned.m8n8.x4.shared.b16 {%0,%1,%2,%3}, [%4];"
                 : "=r"(r[0]), "=r"(r[1]), "=r"(r[2]), "=r"(r[3]) : "r"(addr));
}
__device__ __forceinline__ void ldmx2(uint32_t* r, uint32_t addr) {
    asm volatile("ldmatrix.sync.aligned.m8n8.x2.shared.b16 {%0,%1}, [%2];"
                 : "=r"(r[0]), "=r"(r[1]) : "r"(addr));
}
__device__ __forceinline__ void mma16816(float* c, const uint32_t* a, const uint32_t* b) {
    asm volatile(
        "mma.sync.aligned.m16n8k16.row.col.f32.bf16.bf16.f32 "
        "{%0,%1,%2,%3}, {%4,%5,%6,%7}, {%8,%9}, {%0,%1,%2,%3};"
        : "+f"(c[0]), "+f"(c[1]), "+f"(c[2]), "+f"(c[3])
        : "r"(a[0]), "r"(a[1]), "r"(a[2]), "r"(a[3]), "r"(b[0]), "r"(b[1]));
}
#define CP_ASYNC16(dst_u32, src_ptr) \
    asm volatile("cp.async.cg.shared.global [%0], [%1], 16;" \
                 :: "r"(dst_u32), "l"(src_ptr) : "memory")
#define CP_COMMIT() asm volatile("cp.async.commit_group;" ::: "memory")
#define CP_WAIT1()  asm volatile("cp.async.wait_group 1;"  ::: "memory")

// ---------------------------------------------------------------------------
// Kernel 1 (prep): heterogeneous grid.
//   blocks [0, nb_bucket)          : bucket edges by dst (dtype detected per
//                                    block via warp-0 ballot prologue)
//   blocks [nb_bucket, +256)       : W1 transpose+split
//   blocks [nb_bucket+256, +512)   : W2 transpose+split
// ---------------------------------------------------------------------------
__global__ __launch_bounds__(256)
void prep_kernel(const void* __restrict__ ei, int n_edges, int nb_bucket,
                 const float* __restrict__ W1, const float* __restrict__ W2)
{
    const int b = blockIdx.x;
    const int tid = threadIdx.x;

    if (b < nb_bucket) {
        // ---- per-block dtype detection (warp 0, ballot over 64 odd words) ----
        __shared__ int s_is64;
        if (tid < 32) {
            const int* w = (const int*)ei;
            int nz = (w[2 * tid + 1] != 0) | (w[2 * (tid + 32) + 1] != 0);
            unsigned any = __ballot_sync(0xffffffff, nz);
            if (tid == 0) s_is64 = (any == 0) ? 1 : 0;
        }
        __syncthreads();
        const int is64 = s_is64;

        int base = b * 1024;
        #pragma unroll
        for (int k = 0; k < 4; k++) {
            int e = base + k * 256 + tid;
            if (e < n_edges) {
                int s, d;
                if (is64) {
                    s = (int)((const long long*)ei)[e];
                    d = (int)((const long long*)ei)[n_edges + e];
                } else {
                    s = ((const int*)ei)[e];
                    d = ((const int*)ei)[n_edges + e];
                }
                if (s >= 0 && s < N_NODES && d >= 0 && d < N_NODES) {
                    int pos = atomicAdd(&g_cur[d], 1);
                    if (pos < CAP) {
                        g_bucket[d * CAP + pos] = s;
                    } else {
                        int o = atomicAdd(&g_ovf_cnt, 1);
                        if (o < MAX_OVF) {
                            g_ovf[2 * o] = s;
                            g_ovf[2 * o + 1] = d;
                        }
                    }
                }
            }
        }
    } else if (b < nb_bucket + 256) {
        // ---- W1^T split: [F_IN, F_HID] -> [F_HID, F_IN] hi/lo ----
        int idx = (b - nb_bucket) * 256 + tid;     // < 65536
        int n = idx / F_IN, k = idx % F_IN;
        float v = W1[(size_t)k * F_HID + n];
        __nv_bfloat16 h = __float2bfloat16(v);
        g_w1t_hi[idx] = h;
        g_w1t_lo[idx] = __float2bfloat16(v - __bfloat162float(h));
    } else {
        // ---- W2^T split: [F_HID, F_IN] -> [F_IN, F_HID] hi/lo ----
        int idx = (b - nb_bucket - 256) * 256 + tid;
        int n = idx / F_HID, k = idx % F_HID;
        float v = W2[(size_t)k * F_IN + n];
        __nv_bfloat16 h = __float2bfloat16(v);
        g_w2t_hi[idx] = h;
        g_w2t_lo[idx] = __float2bfloat16(v - __bfloat162float(h));
    }
}

// ---------------------------------------------------------------------------
// Kernel 2: gather-accumulate, warp per node, lane-parallel index loads.
// Tail: reset g_cur[node] = 0 (maintains the zeroed invariant for next run).
// ---------------------------------------------------------------------------
__global__ __launch_bounds__(256)
void gather_kernel(const float* __restrict__ x,
                   const float* __restrict__ eps,
                   __nv_bfloat16* __restrict__ h_hi,
                   __nv_bfloat16* __restrict__ h_lo)
{
    const int warp = (blockIdx.x * blockDim.x + threadIdx.x) >> 5;
    if (warp >= N_NODES) return;
    const int lane = threadIdx.x & 31;

    const int deg  = min(g_cur[warp], CAP);
    const int base = warp * CAP;
    const float s = 1.0f + *eps;

    float4 xv = *reinterpret_cast<const float4*>(x + (size_t)warp * F_IN + lane * 4);
    float4 a0, a1, a2, a3;
    a0.x = xv.x * s; a0.y = xv.y * s; a0.z = xv.z * s; a0.w = xv.w * s;
    a1 = make_float4(0.f, 0.f, 0.f, 0.f);
    a2 = make_float4(0.f, 0.f, 0.f, 0.f);
    a3 = make_float4(0.f, 0.f, 0.f, 0.f);

    for (int b = 0; b < deg; b += 32) {
        const int n = min(32, deg - b);
        int idx = (b + lane < deg) ? g_bucket[base + b + lane] : 0;
        int j = 0;
        for (; j + 3 < n; j += 4) {
            int s0 = __shfl_sync(0xffffffff, idx, j);
            int s1 = __shfl_sync(0xffffffff, idx, j + 1);
            int s2 = __shfl_sync(0xffffffff, idx, j + 2);
            int s3 = __shfl_sync(0xffffffff, idx, j + 3);
            float4 v0 = *reinterpret_cast<const float4*>(x + (size_t)s0 * F_IN + lane * 4);
            float4 v1 = *reinterpret_cast<const float4*>(x + (size_t)s1 * F_IN + lane * 4);
            float4 v2 = *reinterpret_cast<const float4*>(x + (size_t)s2 * F_IN + lane * 4);
            float4 v3 = *reinterpret_cast<const float4*>(x + (size_t)s3 * F_IN + lane * 4);
            a0.x += v0.x; a0.y += v0.y; a0.z += v0.z; a0.w += v0.w;
            a1.x += v1.x; a1.y += v1.y; a1.z += v1.z; a1.w += v1.w;
            a2.x += v2.x; a2.y += v2.y; a2.z += v2.z; a2.w += v2.w;
            a3.x += v3.x; a3.y += v3.y; a3.z += v3.z; a3.w += v3.w;
        }
        for (; j < n; j++) {
            int s0 = __shfl_sync(0xffffffff, idx, j);
            float4 v0 = *reinterpret_cast<const float4*>(x + (size_t)s0 * F_IN + lane * 4);
            a0.x += v0.x; a0.y += v0.y; a0.z += v0.z; a0.w += v0.w;
        }
    }
    a0.x += a1.x + a2.x + a3.x;
    a0.y += a1.y + a2.y + a3.y;
    a0.z += a1.z + a2.z + a3.z;
    a0.w += a1.w + a2.w + a3.w;

    __nv_bfloat16 h0b = __float2bfloat16(a0.x);
    __nv_bfloat16 h1b = __float2bfloat16(a0.y);
    __nv_bfloat16 h2b = __float2bfloat16(a0.z);
    __nv_bfloat16 h3b = __float2bfloat16(a0.w);
    uint2 hv, lv;
    hv.x = pack_bf2(h0b, h1b);
    hv.y = pack_bf2(h2b, h3b);
    lv.x = pack_bf2(__float2bfloat16(a0.x - __bfloat162float(h0b)),
                    __float2bfloat16(a0.y - __bfloat162float(h1b)));
    lv.y = pack_bf2(__float2bfloat16(a0.z - __bfloat162float(h2b)),
                    __float2bfloat16(a0.w - __bfloat162float(h3b)));
    *reinterpret_cast<uint2*>(h_hi + (size_t)warp * F_IN + lane * 4) = hv;
    *reinterpret_cast<uint2*>(h_lo + (size_t)warp * F_IN + lane * 4) = lv;

    // reset counter for the next execution (invariant: g_cur == 0 at entry)
    if (lane == 0) g_cur[warp] = 0;
}

// ---------------------------------------------------------------------------
// Kernel 3: overflow fixup (single warp, serial; empty in practice).
// Tail: reset g_ovf_cnt.
// ---------------------------------------------------------------------------
__global__ void fixup_kernel(const float* __restrict__ x,
                             __nv_bfloat16* __restrict__ h_hi,
                             __nv_bfloat16* __restrict__ h_lo)
{
    const int cnt = min(g_ovf_cnt, MAX_OVF);
    const int lane = threadIdx.x;
    for (int e = 0; e < cnt; e++) {
        int s = g_ovf[2 * e];
        int d = g_ovf[2 * e + 1];
        float4 xv = *reinterpret_cast<const float4*>(x + (size_t)s * F_IN + lane * 4);
        uint2 hv = *reinterpret_cast<uint2*>(h_hi + (size_t)d * F_IN + lane * 4);
        uint2 lv = *reinterpret_cast<uint2*>(h_lo + (size_t)d * F_IN + lane * 4);
        float2 h01 = unpack_bf2(hv.x), h23 = unpack_bf2(hv.y);
        float2 l01 = unpack_bf2(lv.x), l23 = unpack_bf2(lv.y);
        float f0 = h01.x + l01.x + xv.x;
        float f1 = h01.y + l01.y + xv.y;
        float f2 = h23.x + l23.x + xv.z;
        float f3 = h23.y + l23.y + xv.w;
        __nv_bfloat16 n0 = __float2bfloat16(f0);
        __nv_bfloat16 n1 = __float2bfloat16(f1);
        __nv_bfloat16 n2 = __float2bfloat16(f2);
        __nv_bfloat16 n3 = __float2bfloat16(f3);
        hv.x = pack_bf2(n0, n1);
        hv.y = pack_bf2(n2, n3);
        lv.x = pack_bf2(__float2bfloat16(f0 - __bfloat162float(n0)),
                        __float2bfloat16(f1 - __bfloat162float(n1)));
        lv.y = pack_bf2(__float2bfloat16(f2 - __bfloat162float(n2)),
                        __float2bfloat16(f3 - __bfloat162float(n3)));
        *reinterpret_cast<uint2*>(h_hi + (size_t)d * F_IN + lane * 4) = hv;
        *reinterpret_cast<uint2*>(h_lo + (size_t)d * F_IN + lane * 4) = lv;
        __syncwarp();
    }
    if (lane == 0) g_ovf_cnt = 0;
}

// ---------------------------------------------------------------------------
// Fused MLP, BM=64, occupancy 2. cp.async double-buffered weights. (R13)
// ---------------------------------------------------------------------------
__global__ __launch_bounds__(256, 2)
void fused_mlp_kernel(const __nv_bfloat16* __restrict__ A_hi,
                      const __nv_bfloat16* __restrict__ A_lo,
                      const __nv_bfloat16* __restrict__ W1t_hi,
                      const __nv_bfloat16* __restrict__ W1t_lo,
                      const float* __restrict__ b1,
                      const __nv_bfloat16* __restrict__ W2t_hi,
                      const __nv_bfloat16* __restrict__ W2t_lo,
                      const float* __restrict__ b2,
                      float* __restrict__ out,
                      int M)
{
    constexpr int SM_A_HI  = 0;
    constexpr int SM_A_LO  = 16384;
    constexpr int SM_H_HI  = 32768;
    constexpr int SM_H_LO  = 40960;
    constexpr int SM_W1_HI = 49152;
    constexpr int SM_W1_LO = 65536;
    constexpr int SM_W2_HI = 81920;
    constexpr int SM_W2_LO = 98304;

    extern __shared__ __align__(1024) char smem[];
    const uint32_t sbase = smem_to_u32(smem);

    const int tid  = threadIdx.x;
    const int wid  = tid >> 5;
    const int lane = tid & 31;
    const int bm   = blockIdx.x * 64;

    const int wm = wid >> 2;
    const int wn = wid & 3;

    const int a_row = lane & 15;
    const int a_kh  = (lane >> 4) & 1;
    const int b_row = lane & 7;
    const int b_kh  = (lane >> 3) & 1;
    const int er    = lane >> 2;
    const int ec    = (lane & 3) * 2;

    {
        #pragma unroll
        for (int it = 0; it < 4; it++) {
            int slot = tid + it * 256;
            int r  = slot >> 4;
            int c8 = slot & 15;
            uint32_t off = t64r(r, c8 * 8);
            CP_ASYNC16(sbase + SM_W1_HI + off, W1t_hi + (size_t)r * F_IN + c8 * 8);
            CP_ASYNC16(sbase + SM_W1_LO + off, W1t_lo + (size_t)r * F_IN + c8 * 8);
        }
        CP_COMMIT();
    }

    #pragma unroll
    for (int it = 0; it < 4; it++) {
        int slot = tid + it * 256;
        int r  = slot >> 4;
        int c8 = slot & 15;
        int gr = bm + r;
        uint4 hv, lv;
        if (gr < M) {
            hv = *reinterpret_cast<const uint4*>(A_hi + (size_t)gr * F_IN + c8 * 8);
            lv = *reinterpret_cast<const uint4*>(A_lo + (size_t)gr * F_IN + c8 * 8);
        } else {
            hv = make_uint4(0, 0, 0, 0); lv = make_uint4(0, 0, 0, 0);
        }
        uint32_t off = t64r(r, c8 * 8);
        *reinterpret_cast<uint4*>(smem + SM_A_HI + off) = hv;
        *reinterpret_cast<uint4*>(smem + SM_A_LO + off) = lv;
    }

    float acc_out[2][4][4];
    #pragma unroll
    for (int i = 0; i < 2; i++)
        #pragma unroll
        for (int j = 0; j < 4; j++)
            #pragma unroll
            for (int q = 0; q < 4; q++)
                acc_out[i][j][q] = 0.f;

    for (int c = 0; c < 8; c++) {
        __syncthreads();

        #pragma unroll
        for (int it = 0; it < 4; it++) {
            int slot = tid + it * 256;
            int r  = slot >> 3;
            int c8 = slot & 7;
            uint32_t off = t64c(r, c8 * 8);
            const size_t g = (size_t)r * F_HID + c * 64 + c8 * 8;
            CP_ASYNC16(sbase + SM_W2_HI + off, W2t_hi + g);
            CP_ASYNC16(sbase + SM_W2_LO + off, W2t_lo + g);
        }
        CP_COMMIT();
        CP_WAIT1();
        __syncthreads();

        float acc_h[2][2][4];
        #pragma unroll
        for (int i = 0; i < 2; i++)
            #pragma unroll
            for (int j = 0; j < 2; j++)
                #pragma unroll
                for (int q = 0; q < 4; q++)
                    acc_h[i][j][q] = 0.f;

        #pragma unroll
        for (int ks = 0; ks < 8; ks++) {
            uint32_t bh[2][2], bl[2][2];
            #pragma unroll
            for (int nt = 0; nt < 2; nt++) {
                int n = wn * 16 + nt * 8 + b_row;
                uint32_t off = t64r(n, ks * 16 + b_kh * 8);
                ldmx2(bh[nt], sbase + SM_W1_HI + off);
                ldmx2(bl[nt], sbase + SM_W1_LO + off);
            }
            #pragma unroll
            for (int mt = 0; mt < 2; mt++) {
                int m = wm * 32 + mt * 16 + a_row;
                uint32_t off = t64r(m, ks * 16 + a_kh * 8);
                uint32_t ah[4], al[4];
                ldmx4(ah, sbase + SM_A_HI + off);
                ldmx4(al, sbase + SM_A_LO + off);
                #pragma unroll
                for (int nt = 0; nt < 2; nt++) {
                    mma16816(acc_h[mt][nt], ah, bh[nt]);
                    mma16816(acc_h[mt][nt], ah, bl[nt]);
                    mma16816(acc_h[mt][nt], al, bh[nt]);
                }
            }
        }
        __syncthreads();

        if (c + 1 < 8) {
            #pragma unroll
            for (int it = 0; it < 4; it++) {
                int slot = tid + it * 256;
                int r  = slot >> 4;
                int c8 = slot & 15;
                uint32_t off = t64r(r, c8 * 8);
                const size_t g = (size_t)((c + 1) * 64 + r) * F_IN + c8 * 8;
                CP_ASYNC16(sbase + SM_W1_HI + off, W1t_hi + g);
                CP_ASYNC16(sbase + SM_W1_LO + off, W1t_lo + g);
            }
        }
        CP_COMMIT();

        #pragma unroll
        for (int mt = 0; mt < 2; mt++) {
            int lr0 = wm * 32 + mt * 16 + er;
            #pragma unroll
            for (int nt = 0; nt < 2; nt++) {
                int lc = wn * 16 + nt * 8 + ec;
                float bia0 = b1[c * 64 + lc];
                float bia1 = b1[c * 64 + lc + 1];
                #pragma unroll
                for (int h = 0; h < 2; h++) {
                    float v0 = fmaxf(acc_h[mt][nt][2 * h + 0] + bia0, 0.f);
                    float v1 = fmaxf(acc_h[mt][nt][2 * h + 1] + bia1, 0.f);
                    __nv_bfloat16 hh0 = __float2bfloat16(v0);
                    __nv_bfloat16 hh1 = __float2bfloat16(v1);
                    uint32_t off = t64c(lr0 + h * 8, lc);
                    *reinterpret_cast<uint32_t*>(smem + SM_H_HI + off) = pack_bf2(hh0, hh1);
                    *reinterpret_cast<uint32_t*>(smem + SM_H_LO + off) =
                        pack_bf2(__float2bfloat16(v0 - __bfloat162float(hh0)),
                                 __float2bfloat16(v1 - __bfloat162float(hh1)));
                }
            }
        }
        CP_WAIT1();
        __syncthreads();

        #pragma unroll
        for (int ks = 0; ks < 4; ks++) {
            uint32_t bh[4][2], bl[4][2];
            #pragma unroll
            for (int nt = 0; nt < 4; nt++) {
                int n = wn * 32 + nt * 8 + b_row;
                uint32_t off = t64c(n, ks * 16 + b_kh * 8);
                ldmx2(bh[nt], sbase + SM_W2_HI + off);
                ldmx2(bl[nt], sbase + SM_W2_LO + off);
            }
            #pragma unroll
            for (int mt = 0; mt < 2; mt++) {
                int m = wm * 32 + mt * 16 + a_row;
                uint32_t off = t64c(m, ks * 16 + a_kh * 8);
                uint32_t ah[4], al[4];
                ldmx4(ah, sbase + SM_H_HI + off);
                ldmx4(al, sbase + SM_H_LO + off);
                #pragma unroll
                for (int nt = 0; nt < 4; nt++) {
                    mma16816(acc_out[mt][nt], ah, bh[nt]);
                    mma16816(acc_out[mt][nt], ah, bl[nt]);
                    mma16816(acc_out[mt][nt], al, bh[nt]);
                }
            }
        }
    }

    #pragma unroll
    for (int mt = 0; mt < 2; mt++) {
        const int row0 = bm + wm * 32 + mt * 16 + er;
        #pragma unroll
        for (int nt = 0; nt < 4; nt++) {
            const int col = wn * 32 + nt * 8 + ec;
            const float bia0 = b2[col], bia1 = b2[col + 1];
            #pragma unroll
            for (int h = 0; h < 2; h++) {
                const int row = row0 + h * 8;
                if (row >= M) continue;
                float2 v;
                v.x = acc_out[mt][nt][2 * h + 0] + bia0;
                v.y = acc_out[mt][nt][2 * h + 1] + bia1;
                *reinterpret_cast<float2*>(out + (size_t)row * F_IN + col) = v;
            }
        }
    }
}

// ---------------------------------------------------------------------------
// Launch
// ---------------------------------------------------------------------------
extern "C" void kernel_launch(void* const* d_in, const int* in_sizes, int n_in,
                              void* d_out, int out_size)
{
    const float* x   = (const float*)d_in[0];
    const void*  ei  = d_in[1];
    const float* W1  = (const float*)d_in[2];
    const float* b1  = (const float*)d_in[3];
    const float* W2  = (const float*)d_in[4];
    const float* b2  = (const float*)d_in[5];
    const float* eps = (const float*)d_in[6];
    float* out = (float*)d_out;

    const int n_edges = in_sizes[1] / 2;

    __nv_bfloat16 *h0hi, *h0lo, *w1th, *w1tl, *w2th, *w2tl;
    cudaGetSymbolAddress((void**)&h0hi, g_h0_hi);
    cudaGetSymbolAddress((void**)&h0lo, g_h0_lo);
    cudaGetSymbolAddress((void**)&w1th, g_w1t_hi);
    cudaGetSymbolAddress((void**)&w1tl, g_w1t_lo);
    cudaGetSymbolAddress((void**)&w2th, g_w2t_hi);
    cudaGetSymbolAddress((void**)&w2tl, g_w2t_lo);

    // 1) prep: bucket + both weight splits in ONE heterogeneous launch
    {
        const int nb_bucket = (n_edges + 1023) / 1024;
        prep_kernel<<<nb_bucket + 512, 256>>>(ei, n_edges, nb_bucket, W1, W2);
    }

    // 2) gather-accumulate -> split bf16 h0 (resets g_cur); overflow fixup
    {
        const int wpb = 8;
        gather_kernel<<<(N_NODES + wpb - 1) / wpb, wpb * 32>>>(x, eps, h0hi, h0lo);
        fixup_kernel<<<1, 32>>>(x, h0hi, h0lo);
    }

    // 3) fused MLP (BM=64, occupancy 2, cp.async double-buffered weights)
    {
        constexpr int SMEM = 114688;   // 112 KB
        cudaFuncSetAttribute(fused_mlp_kernel,
                             cudaFuncAttributeMaxDynamicSharedMemorySize, SMEM);
        const int mtiles = (N_NODES + 63) / 64;   // 782
        fused_mlp_kernel<<<mtiles, 256, SMEM>>>(
            h0hi, h0lo, w1th, w1tl, b1, w2th, w2tl, b2, out, N_NODES);
    }
}